// round 1
// baseline (speedup 1.0000x reference)
#include <cuda_runtime.h>

// DotInteract: out[b] = concat(dense[b], triu(C C^T)) with C = [dense[b]; sparse[b,0..25]] (27x128)
// B = 32768, D = 128, N = 27, out width = 128 + 378 = 506 floats.

#define R_PER_CTA 4      // batch rows per CTA (one warp per row)
#define NROW      27
#define PAD2      65     // float2 per smem row (130 floats -> avoids 128-stride bank conflicts)
#define K2        64     // float2 per logical row (128 floats)
#define OUTW      506
#define THREADS   128

// Upper-triangular tile enumeration of the 7x7 tile grid (4x4 tiles over padded 28x28)
__constant__ unsigned char cTI[28] = {0,0,0,0,0,0,0, 1,1,1,1,1,1, 2,2,2,2,2, 3,3,3,3, 4,4,4, 5,5, 6};
__constant__ unsigned char cTJ[28] = {0,1,2,3,4,5,6,   1,2,3,4,5,6,   2,3,4,5,6,   3,4,5,6,   4,5,6,   5,6,   6};

union F2U { float2 f; unsigned long long u; };

__device__ __forceinline__ float2 ffma2(float2 a, float2 b, float2 c) {
    F2U A, B, C, D;
    A.f = a; B.f = b; C.f = c;
    asm("fma.rn.f32x2 %0, %1, %2, %3;" : "=l"(D.u) : "l"(A.u), "l"(B.u), "l"(C.u));
    return D.f;
}

extern __shared__ float2 sm[];   // [R_PER_CTA][27][PAD2] float2

__global__ void __launch_bounds__(THREADS, 4)
dot_interact_kernel(const float* __restrict__ dense,
                    const float* __restrict__ sparse,
                    float* __restrict__ out, int B)
{
    const int b0  = blockIdx.x * R_PER_CTA;
    const int tid = threadIdx.x;

    const float2* dense2  = reinterpret_cast<const float2*>(dense);
    const float2* sparse2 = reinterpret_cast<const float2*>(sparse);
    float2*       out2    = reinterpret_cast<float2*>(out);

    // ---- Load phase: stage C tiles into smem (coalesced), fuse dense passthrough ----
    #pragma unroll 1
    for (int idx = tid; idx < R_PER_CTA * NROW * K2; idx += THREADS) {
        int i   = idx / (NROW * K2);
        int rem = idx - i * (NROW * K2);
        int r   = rem / K2;
        int k2  = rem - r * K2;
        int b   = b0 + i;
        if (b < B) {
            float2 v = (r == 0)
                     ? dense2[(long long)b * K2 + k2]
                     : sparse2[((long long)b * 26 + (r - 1)) * K2 + k2];
            sm[(i * NROW + r) * PAD2 + k2] = v;
            if (r == 0) out2[(long long)b * (OUTW / 2) + k2] = v;  // dense passthrough
        }
    }
    __syncthreads();

    // ---- Compute phase: warp w handles batch row b0+w ----
    const int w    = tid >> 5;
    const int lane = tid & 31;
    const int b    = b0 + w;
    if (lane >= 28 || b >= B) return;

    const float2* base = sm + w * NROW * PAD2;
    const int ti = cTI[lane];
    const int tj = cTJ[lane];

    const float2* ar[4];
    const float2* bc[4];
    #pragma unroll
    for (int u = 0; u < 4; u++) {
        int r = 4 * ti + u; if (r > 26) r = 26;   // clamp (tile row 27 is discarded at write)
        int c = 4 * tj + u; if (c > 26) c = 26;
        ar[u] = base + r * PAD2;
        bc[u] = base + c * PAD2;
    }

    float2 acc[4][4];
    #pragma unroll
    for (int u = 0; u < 4; u++)
        #pragma unroll
        for (int v = 0; v < 4; v++)
            acc[u][v] = make_float2(0.f, 0.f);

    #pragma unroll 4
    for (int k = 0; k < K2; k++) {
        float2 a0 = ar[0][k], a1 = ar[1][k], a2 = ar[2][k], a3 = ar[3][k];
        float2 q0 = bc[0][k], q1 = bc[1][k], q2 = bc[2][k], q3 = bc[3][k];
        acc[0][0] = ffma2(a0, q0, acc[0][0]);
        acc[0][1] = ffma2(a0, q1, acc[0][1]);
        acc[0][2] = ffma2(a0, q2, acc[0][2]);
        acc[0][3] = ffma2(a0, q3, acc[0][3]);
        acc[1][0] = ffma2(a1, q0, acc[1][0]);
        acc[1][1] = ffma2(a1, q1, acc[1][1]);
        acc[1][2] = ffma2(a1, q2, acc[1][2]);
        acc[1][3] = ffma2(a1, q3, acc[1][3]);
        acc[2][0] = ffma2(a2, q0, acc[2][0]);
        acc[2][1] = ffma2(a2, q1, acc[2][1]);
        acc[2][2] = ffma2(a2, q2, acc[2][2]);
        acc[2][3] = ffma2(a2, q3, acc[2][3]);
        acc[3][0] = ffma2(a3, q0, acc[3][0]);
        acc[3][1] = ffma2(a3, q1, acc[3][1]);
        acc[3][2] = ffma2(a3, q2, acc[3][2]);
        acc[3][3] = ffma2(a3, q3, acc[3][3]);
    }

    // ---- Write phase: upper triangle, row-major triu order ----
    float* orow = out + (long long)b * OUTW + 128;
    #pragma unroll
    for (int u = 0; u < 4; u++) {
        int r = 4 * ti + u;
        if (r > 26) continue;
        int rbase = 26 * r - (r * (r - 1)) / 2;   // triu(r,c) index = rbase + c
        #pragma unroll
        for (int v = 0; v < 4; v++) {
            int c = 4 * tj + v;
            if (c > 26 || c < r) continue;
            orow[rbase + c] = acc[u][v].x + acc[u][v].y;
        }
    }
}

extern "C" void kernel_launch(void* const* d_in, const int* in_sizes, int n_in,
                              void* d_out, int out_size)
{
    const float* dense  = (const float*)d_in[0];
    const float* sparse = (const float*)d_in[1];
    float*       out    = (float*)d_out;

    int B = in_sizes[0] / 128;
    size_t smem = (size_t)R_PER_CTA * NROW * PAD2 * sizeof(float2);  // 56,160 B

    static bool attr_set = false;  // idempotent attribute, not a memory op
    cudaFuncSetAttribute(dot_interact_kernel,
                         cudaFuncAttributeMaxDynamicSharedMemorySize, (int)smem);

    int grid = (B + R_PER_CTA - 1) / R_PER_CTA;
    dot_interact_kernel<<<grid, THREADS, smem>>>(dense, sparse, out, B);
    (void)attr_set; (void)n_in; (void)out_size;
}

// round 3
// speedup vs baseline: 1.9593x; 1.9593x over previous
#include <cuda_runtime.h>

// DotInteract: out[b] = concat(dense[b] (128), triu(C C^T) (378)) with
// C = [dense[b]; sparse[b,0..25]] (27 x 128).  B = 32768, OUTW = 506.
//
// One warp per batch row. Lane j holds row j's 4-float k-chunk in registers
// ("own"); the warp broadcasts row i's chunk from smem (single-address
// LDS.128 = 1 wavefront) and does 2 FFMA2 into acc[i].  acc[i] is touched
// once per 27-iteration sweep -> no FFMA RAW chain.  Smem is a per-warp
// 27x32-float staging block (9-float4 row stride => conflict-free own loads).

#define NROW    27
#define THREADS 128
#define WPC     4          // warps (batch rows) per CTA
#define OUTW    506
#define SROW    9          // float4 stride per smem row (pad 8 -> 9)
#define SWARP   (NROW * SROW)   // 243 float4 per warp

union F2U { float2 f; unsigned long long u; };

__device__ __forceinline__ float2 ffma2(float2 a, float2 b, float2 c) {
    F2U A, B, C, D;
    A.f = a; B.f = b; C.f = c;
    asm("fma.rn.f32x2 %0, %1, %2, %3;" : "=l"(D.u) : "l"(A.u), "l"(B.u), "l"(C.u));
    return D.f;
}

extern __shared__ float4 sm4[];   // [WPC][SWARP]

__global__ void __launch_bounds__(THREADS, 4)
dot_interact_kernel(const float4* __restrict__ dense4,
                    const float4* __restrict__ sparse4,
                    float* __restrict__ out, int B)
{
    const int warp = threadIdx.x >> 5;
    const int lane = threadIdx.x & 31;
    const int b    = blockIdx.x * WPC + warp;
    if (b >= B) return;                      // warp-uniform exit; no CTA barriers used

    float4* s = sm4 + warp * SWARP;
    const int jc = (lane < NROW) ? lane : (NROW - 1);   // lanes 27..31 shadow row 26

    float2 acc[NROW];
    #pragma unroll
    for (int i = 0; i < NROW; i++) acc[i] = make_float2(0.f, 0.f);

    const float4* dbase = dense4  + (long long)b * 32;        // 128 floats = 32 float4
    const float4* sbase = sparse4 + (long long)b * 26 * 32;
    float2* outd = reinterpret_cast<float2*>(out) + (long long)b * (OUTW / 2);

    #pragma unroll 1
    for (int blk = 0; blk < 4; blk++) {      // k-blocks of 32 floats (8 float4)
        // ---- stage 27 rows x 8 float4 into smem; fuse dense passthrough ----
        #pragma unroll
        for (int it = 0; it < 7; it++) {
            int idx = it * 32 + lane;        // 0..223, need < 216
            if (idx < 216) {
                int r  = idx >> 3;
                int c4 = idx & 7;
                float4 v = (r == 0) ? dbase[blk * 8 + c4]
                                    : sbase[(r - 1) * 32 + blk * 8 + c4];
                s[r * SROW + c4] = v;
                if (r == 0) {                // dense passthrough (it==0, lanes 0..7)
                    outd[blk * 16 + c4 * 2]     = make_float2(v.x, v.y);
                    outd[blk * 16 + c4 * 2 + 1] = make_float2(v.z, v.w);
                }
            }
        }
        __syncwarp();

        // ---- compute: for each 4-float chunk, sweep all 27 broadcast rows ----
        #pragma unroll
        for (int c4 = 0; c4 < 8; c4++) {
            float4 own = s[jc * SROW + c4];
            float2 o01 = make_float2(own.x, own.y);
            float2 o23 = make_float2(own.z, own.w);
            #pragma unroll
            for (int i = 0; i < NROW; i++) {
                float4 bc = s[i * SROW + c4];            // single-address broadcast
                acc[i] = ffma2(make_float2(bc.x, bc.y), o01, acc[i]);
                acc[i] = ffma2(make_float2(bc.z, bc.w), o23, acc[i]);
            }
        }
        __syncwarp();                        // WAR: block reuse next iteration
    }

    // ---- epilogue: lane j writes triu column j: gram(i, j) for i <= j ----
    if (lane < NROW) {
        float* orow = out + (long long)b * OUTW + 128;
        #pragma unroll
        for (int i = 0; i < NROW; i++) {
            if (i <= lane) {
                orow[26 * i - (i * (i - 1)) / 2 + lane] = acc[i].x + acc[i].y;
            }
        }
    }
}

extern "C" void kernel_launch(void* const* d_in, const int* in_sizes, int n_in,
                              void* d_out, int out_size)
{
    const float4* dense4  = (const float4*)d_in[0];
    const float4* sparse4 = (const float4*)d_in[1];
    float*        out     = (float*)d_out;

    int B = in_sizes[0] / 128;
    int grid = (B + WPC - 1) / WPC;
    size_t smem = (size_t)WPC * SWARP * sizeof(float4);   // 15,552 B

    dot_interact_kernel<<<grid, THREADS, smem>>>(dense4, sparse4, out, B);
    (void)n_in; (void)out_size;
}

// round 4
// speedup vs baseline: 3.2259x; 1.6464x over previous
#include <cuda_runtime.h>

// DotInteract: out[b] = concat(dense[b] (128), triu(C C^T) (378)),
// C = [dense[b]; sparse[b,0..25]] (27 x 128). B = 32768, OUTW = 506.
//
// One warp per sample. Lane = one 4x4 tile of the upper-triangular 7x7 tile
// grid over the padded 28x28 Gram matrix. Per 4-float k-chunk each lane does
// 8 LDS.128 (4 a-rows + 4 b-cols) -> 32 FFMA2 (f32x2), amortizing the smem
// crossbar ~4x vs a broadcast scheme. Rows live at permuted slots
// sigma(r) = (r%4)*7 + r/4 so each a/b load's 7 distinct rows hit 7 distinct
// 16B banks (SROW=9). Global data for the next 32-float k-block is prefetched
// into registers before compute to hide LDG latency.

#define NROW    27
#define THREADS 128
#define WPC     4
#define OUTW    506
#define SROW    9                 // float4 stride per slot
#define NSLOT   28
#define SWARP   (NSLOT * SROW)    // 252 float4 per warp

// tile coords per lane; lanes 28..31 duplicate tile (6,6) and never write
__constant__ unsigned char cTI[32] = {0,0,0,0,0,0,0, 1,1,1,1,1,1, 2,2,2,2,2,
                                      3,3,3,3, 4,4,4, 5,5, 6, 6,6,6,6};
__constant__ unsigned char cTJ[32] = {0,1,2,3,4,5,6, 1,2,3,4,5,6, 2,3,4,5,6,
                                      3,4,5,6, 4,5,6, 5,6, 6, 6,6,6,6};

union F2U { float2 f; unsigned long long u; };

__device__ __forceinline__ float2 ffma2(float2 a, float2 b, float2 c) {
    F2U A, B, C, D;
    A.f = a; B.f = b; C.f = c;
    asm("fma.rn.f32x2 %0, %1, %2, %3;" : "=l"(D.u) : "l"(A.u), "l"(B.u), "l"(C.u));
    return D.f;
}

extern __shared__ float4 sm4[];   // [WPC][SWARP]

__global__ void __launch_bounds__(THREADS, 4)
dot_interact_kernel(const float4* __restrict__ dense4,
                    const float4* __restrict__ sparse4,
                    float* __restrict__ out, int B)
{
    const int warp = threadIdx.x >> 5;
    const int lane = threadIdx.x & 31;
    const int b    = blockIdx.x * WPC + warp;
    if (b >= B) return;

    float4* s = sm4 + warp * SWARP;
    const int ti = cTI[lane];
    const int tj = cTJ[lane];

    // per-lane staging plan: it = 0..6, idx = it*32+lane covers 0..215
    const float4* dbase = dense4  + (long long)b * 32;
    const float4* sbase = sparse4 + (long long)b * 26 * 32;
    const float4* gp[7];       // global base per it (advance by blk*8)
    int           sa[7];       // smem float4 slot-address per it
    bool          act[7], isd[7];
    #pragma unroll
    for (int it = 0; it < 7; it++) {
        int idx = it * 32 + lane;
        act[it] = (idx < 216);
        int r  = idx >> 3;
        int c4 = idx & 7;
        isd[it] = (r == 0);
        int slot = (r & 3) * 7 + (r >> 2);              // sigma(r)
        sa[it] = slot * SROW + c4;
        gp[it] = act[it] ? ((r == 0) ? (dbase + c4) : (sbase + (r - 1) * 32 + c4))
                         : dbase;                        // harmless dummy
    }

    // a/b slot bases for compute
    int au[4], bv[4];
    #pragma unroll
    for (int u = 0; u < 4; u++) { au[u] = (u * 7 + ti) * SROW; bv[u] = (u * 7 + tj) * SROW; }

    float2 acc[4][4];
    #pragma unroll
    for (int u = 0; u < 4; u++)
        #pragma unroll
        for (int v = 0; v < 4; v++) acc[u][v] = make_float2(0.f, 0.f);

    float2* outd = reinterpret_cast<float2*>(out) + (long long)b * (OUTW / 2);

    // prefetch k-block 0
    float4 g[7];
    #pragma unroll
    for (int it = 0; it < 7; it++) if (act[it]) g[it] = gp[it][0];

    #pragma unroll 1
    for (int blk = 0; blk < 4; blk++) {
        // ---- stage registers -> smem; fuse dense passthrough; zero slot 27 ----
        #pragma unroll
        for (int it = 0; it < 7; it++) {
            if (act[it]) {
                s[sa[it]] = g[it];
                if (isd[it]) {                            // it==0, lanes 0..7
                    outd[blk * 16 + lane * 2]     = make_float2(g[it].x, g[it].y);
                    outd[blk * 16 + lane * 2 + 1] = make_float2(g[it].z, g[it].w);
                }
            }
        }
        if (lane < 8) s[27 * SROW + lane] = make_float4(0.f, 0.f, 0.f, 0.f);
        __syncwarp();

        // ---- prefetch next k-block while computing this one ----
        if (blk < 3) {
            #pragma unroll
            for (int it = 0; it < 7; it++) if (act[it]) g[it] = gp[it][(blk + 1) * 8];
        }

        // ---- compute: 8 chunks x (8 LDS.128 -> 32 FFMA2) ----
        #pragma unroll
        for (int c4 = 0; c4 < 8; c4++) {
            float4 a0 = s[au[0] + c4], a1 = s[au[1] + c4];
            float4 a2 = s[au[2] + c4], a3 = s[au[3] + c4];
            float4 q0 = s[bv[0] + c4], q1 = s[bv[1] + c4];
            float4 q2 = s[bv[2] + c4], q3 = s[bv[3] + c4];
            float2 a01[4] = { make_float2(a0.x,a0.y), make_float2(a1.x,a1.y),
                              make_float2(a2.x,a2.y), make_float2(a3.x,a3.y) };
            float2 a23[4] = { make_float2(a0.z,a0.w), make_float2(a1.z,a1.w),
                              make_float2(a2.z,a2.w), make_float2(a3.z,a3.w) };
            float2 q01[4] = { make_float2(q0.x,q0.y), make_float2(q1.x,q1.y),
                              make_float2(q2.x,q2.y), make_float2(q3.x,q3.y) };
            float2 q23[4] = { make_float2(q0.z,q0.w), make_float2(q1.z,q1.w),
                              make_float2(q2.z,q2.w), make_float2(q3.z,q3.w) };
            #pragma unroll
            for (int u = 0; u < 4; u++)
                #pragma unroll
                for (int v = 0; v < 4; v++) {
                    acc[u][v] = ffma2(a01[u], q01[v], acc[u][v]);
                    acc[u][v] = ffma2(a23[u], q23[v], acc[u][v]);
                }
        }
        __syncwarp();   // WAR before restaging
    }

    // ---- epilogue: write triu entries owned by this lane ----
    if (lane < 28) {
        float* orow = out + (long long)b * OUTW + 128;
        #pragma unroll
        for (int u = 0; u < 4; u++) {
            int r = 4 * ti + u;
            if (r > 26) continue;
            int rbase = 26 * r - (r * (r - 1)) / 2;       // triu(r,c) -> rbase + c
            #pragma unroll
            for (int v = 0; v < 4; v++) {
                int c = 4 * tj + v;
                if (c > 26 || c < r) continue;
                orow[rbase + c] = acc[u][v].x + acc[u][v].y;
            }
        }
    }
}

extern "C" void kernel_launch(void* const* d_in, const int* in_sizes, int n_in,
                              void* d_out, int out_size)
{
    const float4* dense4  = (const float4*)d_in[0];
    const float4* sparse4 = (const float4*)d_in[1];
    float*        out     = (float*)d_out;

    int B = in_sizes[0] / 128;
    int grid = (B + WPC - 1) / WPC;
    size_t smem = (size_t)WPC * SWARP * sizeof(float4);   // 16,128 B

    dot_interact_kernel<<<grid, THREADS, smem>>>(dense4, sparse4, out, B);
    (void)n_in; (void)out_size;
}

// round 7
// speedup vs baseline: 4.6230x; 1.4331x over previous
#include <cuda_runtime.h>
#include <cuda_bf16.h>
#include <cstdint>

// DotInteract: out[b] = concat(dense[b] (128), triu(C C^T) (378)),
// C = [dense[b]; sparse[b,0..25]] (27x128 fp32). B = 32768, OUTW = 506.
//
// One warp per sample, Gram via mma.sync.m16n8k16 bf16 (sm_100-safe HMMA).
// fp32 = bf16 hi + bf16 lo; D = hi.hi^T + hi.lo^T + lo.hi^T (err ~1e-5).
// For row.col mma, A and B fragments ldmatrix'd (non-trans) from the SAME
// row-major tile give D = C.C^T, so one ldmatrix.x4 per 16 rows per k-step
// feeds both operands. Tiles: 32 rows x 32 bf16, row stride 80 B (5 x 16B
// units -> (5r+u) mod 8 is a permutation: conflict-free LDSM).

#define THREADS 128
#define WPC     4            // warps = samples per CTA
#define OUTW    506
#define TSTRIDE 80           // bytes per tile row
#define TBYTES  (32 * TSTRIDE)      // 2560 per split tile
#define WBYTES  (2 * TBYTES)        // hi + lo = 5120 per warp (also epilogue stage)

__device__ __forceinline__ uint32_t smem_u32(const void* p) {
    uint32_t a;
    asm("{ .reg .u64 t; cvta.to.shared.u64 t, %1; cvt.u32.u64 %0, t; }" : "=r"(a) : "l"(p));
    return a;
}
__device__ __forceinline__ uint32_t pack_bf16x2(float lo, float hi) {
    uint32_t r;  // d = { cvt(a)=hi | cvt(b)=lo }
    asm("cvt.rn.bf16x2.f32 %0, %1, %2;" : "=r"(r) : "f"(hi), "f"(lo));
    return r;
}
__device__ __forceinline__ float bf_lo(uint32_t p) { return __uint_as_float(p << 16); }
__device__ __forceinline__ float bf_hi(uint32_t p) { return __uint_as_float(p & 0xFFFF0000u); }

__device__ __forceinline__ void ldsm4(uint32_t* r, uint32_t addr) {
    asm volatile("ldmatrix.sync.aligned.m8n8.x4.shared.b16 {%0,%1,%2,%3}, [%4];"
                 : "=r"(r[0]), "=r"(r[1]), "=r"(r[2]), "=r"(r[3]) : "r"(addr));
}
__device__ __forceinline__ void mma16816(float* d, const uint32_t* a,
                                         uint32_t b0, uint32_t b1) {
    asm volatile("mma.sync.aligned.m16n8k16.row.col.f32.bf16.bf16.f32 "
                 "{%0,%1,%2,%3}, {%4,%5,%6,%7}, {%8,%9}, {%0,%1,%2,%3};"
                 : "+f"(d[0]), "+f"(d[1]), "+f"(d[2]), "+f"(d[3])
                 : "r"(a[0]), "r"(a[1]), "r"(a[2]), "r"(a[3]), "r"(b0), "r"(b1));
}
// 6 triu tiles of the 32x32 Gram: (0,0)(0,1)(0,2)(0,3)(1,2)(1,3); S = A-split
// row-group frags, T = B-split row-group frags.
__device__ __forceinline__ void do_pair(float* c00, float* c01, float* c02, float* c03,
                                        float* c12, float* c13,
                                        const uint32_t* S0, const uint32_t* S1,
                                        const uint32_t* T0, const uint32_t* T1) {
    mma16816(c00, S0, T0[0], T0[2]);
    mma16816(c01, S0, T0[1], T0[3]);
    mma16816(c02, S0, T1[0], T1[2]);
    mma16816(c03, S0, T1[1], T1[3]);
    mma16816(c12, S1, T1[0], T1[2]);
    mma16816(c13, S1, T1[1], T1[3]);
}

extern __shared__ char smem[];

__global__ void __launch_bounds__(THREADS)
dot_interact_mma(const float4* __restrict__ dense4,
                 const float4* __restrict__ sparse4,
                 float* __restrict__ out, int B)
{
    const int warp = threadIdx.x >> 5;
    const int lane = threadIdx.x & 31;
    const int b    = blockIdx.x * WPC + warp;
    if (b >= B) return;

    const uint32_t hiBase = smem_u32(smem) + warp * WBYTES;
    const uint32_t loBase = hiBase + TBYTES;

    // ---- zero pad rows 27..31 of both tiles (once) ----
    #pragma unroll
    for (int it = 0; it < 3; it++) {
        int idx = it * 32 + lane;                 // 0..79, need < 80
        if (idx < 80) {
            int t   = idx >= 40;
            int rem = idx - t * 40;
            int r   = 27 + (rem >> 3);
            int c4  = rem & 7;
            uint32_t ad = (t ? loBase : hiBase) + r * TSTRIDE + (c4 >> 1) * 16 + (c4 & 1) * 8;
            asm volatile("st.shared.v2.b32 [%0], {%1, %1};" :: "r"(ad), "r"(0u));
        }
    }

    // ---- per-lane staging plan: idx = it*32+lane in [0,216) -> (row, c4) ----
    const float4* gp[7];
    uint32_t sOff[7];
    bool act[7];
    #pragma unroll
    for (int it = 0; it < 7; it++) {
        int idx = it * 32 + lane;
        act[it] = (idx < 216);
        int r  = idx >> 3;                        // C row 0..26
        int c4 = idx & 7;                         // float4 within 32-col chunk
        sOff[it] = (uint32_t)(r * TSTRIDE + (c4 >> 1) * 16 + (c4 & 1) * 8);
        gp[it] = act[it]
               ? ((r == 0) ? (dense4 + (long long)b * 32 + c4)
                           : (sparse4 + ((long long)b * 26 + (r - 1)) * 32 + c4))
               : (dense4 + (long long)b * 32);    // inactive dummy
    }

    float c00[4] = {0,0,0,0}, c01[4] = {0,0,0,0}, c02[4] = {0,0,0,0};
    float c03[4] = {0,0,0,0}, c12[4] = {0,0,0,0}, c13[4] = {0,0,0,0};

    float2* out2 = reinterpret_cast<float2*>(out) + (long long)b * (OUTW / 2);

    // ldmatrix lane address pieces: tile = lane>>3 selects (row8, k-unit)
    const int lrow = ((lane >> 3) & 1) * 8 + (lane & 7);
    const int lu   = lane >> 4;                   // 0 or 1 (k-unit within k-step)

    // prefetch chunk 0
    float4 g[7];
    #pragma unroll
    for (int it = 0; it < 7; it++) if (act[it]) g[it] = gp[it][0];

    #pragma unroll 1
    for (int kc = 0; kc < 4; kc++) {
        // ---- stage: convert fp32 -> bf16 hi/lo, store; dense passthrough ----
        #pragma unroll
        for (int it = 0; it < 7; it++) {
            if (act[it]) {
                float4 v = g[it];
                uint32_t h01 = pack_bf16x2(v.x, v.y);
                uint32_t h23 = pack_bf16x2(v.z, v.w);
                uint32_t l01 = pack_bf16x2(v.x - bf_lo(h01), v.y - bf_hi(h01));
                uint32_t l23 = pack_bf16x2(v.z - bf_lo(h23), v.w - bf_hi(h23));
                asm volatile("st.shared.v2.b32 [%0], {%1, %2};"
                             :: "r"(hiBase + sOff[it]), "r"(h01), "r"(h23));
                asm volatile("st.shared.v2.b32 [%0], {%1, %2};"
                             :: "r"(loBase + sOff[it]), "r"(l01), "r"(l23));
                if (it == 0) {                    // row 0 = dense, lanes 0..7
                    out2[kc * 16 + lane * 2]     = make_float2(v.x, v.y);
                    out2[kc * 16 + lane * 2 + 1] = make_float2(v.z, v.w);
                }
            }
        }
        __syncwarp();

        // ---- prefetch next chunk during compute ----
        if (kc < 3) {
            #pragma unroll
            for (int it = 0; it < 7; it++) if (act[it]) g[it] = gp[it][(kc + 1) * 8];
        }

        // ---- compute: 2 k-steps x (4 LDSM.x4 + 18 HMMA) ----
        #pragma unroll
        for (int ks = 0; ks < 2; ks++) {
            uint32_t off0 = (uint32_t)(lrow * TSTRIDE + (2 * ks + lu) * 16);
            uint32_t H0[4], H1[4], L0[4], L1[4];
            ldsm4(H0, hiBase + off0);
            ldsm4(H1, hiBase + off0 + 16 * TSTRIDE);
            ldsm4(L0, loBase + off0);
            ldsm4(L1, loBase + off0 + 16 * TSTRIDE);
            do_pair(c00, c01, c02, c03, c12, c13, H0, H1, H0, H1);  // hi.hi
            do_pair(c00, c01, c02, c03, c12, c13, H0, H1, L0, L1);  // hi.lo
            do_pair(c00, c01, c02, c03, c12, c13, L0, L1, H0, H1);  // lo.hi
        }
        __syncwarp();    // WAR before restaging
    }

    // ---- epilogue: frags -> smem gram[32][33], then triu scatter ----
    float* gstage = reinterpret_cast<float*>(smem + warp * WBYTES);
    {
        const int fr = lane >> 2;                 // 0..7
        const int fc = 2 * (lane & 3);            // 0,2,4,6
        float* t[6] = {c00, c01, c02, c03, c12, c13};
        const int mi[6] = {0, 0, 0, 0, 16, 16};
        const int nj[6] = {0, 8, 16, 24, 16, 24};
        #pragma unroll
        for (int q = 0; q < 6; q++) {
            int r0 = mi[q] + fr, c0 = nj[q] + fc;
            gstage[r0 * 33 + c0]           = t[q][0];
            gstage[r0 * 33 + c0 + 1]       = t[q][1];
            gstage[(r0 + 8) * 33 + c0]     = t[q][2];
            gstage[(r0 + 8) * 33 + c0 + 1] = t[q][3];
        }
    }
    __syncwarp();

    {   // lane j writes gram[i][j] for i <= j; per-i stores are coalesced
        float* orow = out + (long long)b * OUTW + 128;
        #pragma unroll 1
        for (int i = 0; i < 27; i++) {
            if (lane < 27 && i <= lane) {
                orow[26 * i - (i * (i - 1)) / 2 + lane] = gstage[i * 33 + lane];
            }
        }
    }
}

extern "C" void kernel_launch(void* const* d_in, const int* in_sizes, int n_in,
                              void* d_out, int out_size)
{
    const float4* dense4  = (const float4*)d_in[0];
    const float4* sparse4 = (const float4*)d_in[1];
    float*        out     = (float*)d_out;

    int B = in_sizes[0] / 128;
    int grid = (B + WPC - 1) / WPC;
    size_t smem_sz = (size_t)WPC * WBYTES;        // 20,480 B

    dot_interact_mma<<<grid, THREADS, smem_sz>>>(dense4, sparse4, out, B);
    (void)n_in; (void)out_size;
}

// round 8
// speedup vs baseline: 4.7969x; 1.0376x over previous
#include <cuda_runtime.h>
#include <cuda_bf16.h>
#include <cstdint>

// DotInteract: out[b] = concat(dense[b] (128), triu(C C^T) (378)),
// C = [dense[b]; sparse[b,0..25]] (27x128 fp32). B = 32768, OUTW = 506.
//
// One warp per sample, Gram via mma.sync.m16n8k16 bf16 (sm_100-safe HMMA).
// fp32 = bf16 hi + bf16 lo; D = hi.hi^T + hi.lo^T + lo.hi^T (err ~1e-5).
// A and B fragments ldmatrix'd (non-trans) from the SAME row-major tile give
// D = C.C^T. Tiles: 32 rows x 32 bf16, row stride 80 B (conflict-free LDSM).
// R8: affine staging plan (1 running pointer, 1 affine smem offset), no
// register prefetch; occupancy (6 CTAs/SM) hides LDG latency instead.

#define THREADS 128
#define WPC     4            // warps = samples per CTA
#define OUTW    506
#define TSTRIDE 80           // bytes per tile row
#define TBYTES  (32 * TSTRIDE)      // 2560 per split tile
#define WBYTES  (2 * TBYTES)        // hi + lo = 5120 per warp (also epilogue stage)

__device__ __forceinline__ uint32_t smem_u32(const void* p) {
    uint32_t a;
    asm("{ .reg .u64 t; cvta.to.shared.u64 t, %1; cvt.u32.u64 %0, t; }" : "=r"(a) : "l"(p));
    return a;
}
__device__ __forceinline__ uint32_t pack_bf16x2(float lo, float hi) {
    uint32_t r;  // d = { cvt(a)=hi16 | cvt(b)=lo16 }
    asm("cvt.rn.bf16x2.f32 %0, %1, %2;" : "=r"(r) : "f"(hi), "f"(lo));
    return r;
}
__device__ __forceinline__ float bf_lo(uint32_t p) { return __uint_as_float(p << 16); }
__device__ __forceinline__ float bf_hi(uint32_t p) { return __uint_as_float(p & 0xFFFF0000u); }

__device__ __forceinline__ void ldsm4(uint32_t* r, uint32_t addr) {
    asm volatile("ldmatrix.sync.aligned.m8n8.x4.shared.b16 {%0,%1,%2,%3}, [%4];"
                 : "=r"(r[0]), "=r"(r[1]), "=r"(r[2]), "=r"(r[3]) : "r"(addr));
}
__device__ __forceinline__ void mma16816(float* d, const uint32_t* a,
                                         uint32_t b0, uint32_t b1) {
    asm volatile("mma.sync.aligned.m16n8k16.row.col.f32.bf16.bf16.f32 "
                 "{%0,%1,%2,%3}, {%4,%5,%6,%7}, {%8,%9}, {%0,%1,%2,%3};"
                 : "+f"(d[0]), "+f"(d[1]), "+f"(d[2]), "+f"(d[3])
                 : "r"(a[0]), "r"(a[1]), "r"(a[2]), "r"(a[3]), "r"(b0), "r"(b1));
}
// 6 triu tiles of the 32x32 Gram: rows 0-15 x all cols, rows 16-31 x cols 16-31.
__device__ __forceinline__ void do_pair(float* c00, float* c01, float* c02, float* c03,
                                        float* c12, float* c13,
                                        const uint32_t* S0, const uint32_t* S1,
                                        const uint32_t* T0, const uint32_t* T1) {
    mma16816(c00, S0, T0[0], T0[2]);
    mma16816(c01, S0, T0[1], T0[3]);
    mma16816(c02, S0, T1[0], T1[2]);
    mma16816(c03, S0, T1[1], T1[3]);
    mma16816(c12, S1, T1[0], T1[2]);
    mma16816(c13, S1, T1[1], T1[3]);
}

extern __shared__ char smem[];

__global__ void __launch_bounds__(THREADS, 6)
dot_interact_mma(const float4* __restrict__ dense4,
                 const float4* __restrict__ sparse4,
                 float* __restrict__ out, int B)
{
    const int warp = threadIdx.x >> 5;
    const int lane = threadIdx.x & 31;
    const int b    = blockIdx.x * WPC + warp;
    if (b >= B) return;

    const uint32_t hiBase = smem_u32(smem) + warp * WBYTES;
    const uint32_t loBase = hiBase + TBYTES;

    // ---- zero pad rows 27..31 of both tiles (once) ----
    #pragma unroll
    for (int it = 0; it < 3; it++) {
        int idx = it * 32 + lane;                 // need < 80
        if (idx < 80) {
            int t   = idx >= 40;
            int rem = idx - t * 40;
            uint32_t ad = (t ? loBase : hiBase) + (27 + (rem >> 3)) * TSTRIDE + (rem & 7) * 8;
            asm volatile("st.shared.v2.b32 [%0], {%1, %1};" :: "r"(ad), "r"(0u));
        }
    }

    // ---- affine staging plan: it = 0..6, row r = r0 + 4*it, c4 = lane&7 ----
    const int r0 = lane >> 3;                     // 0..3
    const int c4 = lane & 7;
    const bool dlane   = (r0 == 0);               // it==0 reads dense for these lanes
    const bool tail_ok = (lane < 24);             // it==6 active only for lanes 0..23
    const float4* dptr = dense4 + (long long)b * 32 + c4;
    // valid for it>=1 always; for it==0 only when r0>=1 (dlane handles r0==0)
    const float4* sptr = sparse4 + ((long long)b * 26 + (r0 - 1)) * 32 + c4;
    const uint32_t sOff0 = (uint32_t)(r0 * TSTRIDE + c4 * 8);

    float c00[4] = {0,0,0,0}, c01[4] = {0,0,0,0}, c02[4] = {0,0,0,0};
    float c03[4] = {0,0,0,0}, c12[4] = {0,0,0,0}, c13[4] = {0,0,0,0};

    float2* out2 = reinterpret_cast<float2*>(out) + (long long)b * (OUTW / 2);

    // ldmatrix lane address pieces
    const int lrow = ((lane >> 3) & 1) * 8 + (lane & 7);
    const int lu   = lane >> 4;                   // k-unit within k-step

    #pragma unroll 1
    for (int kc = 0; kc < 4; kc++) {
        const float4* sp = sptr + kc * 8;
        // ---- stage: LDG -> split bf16 hi/lo -> STS; dense passthrough ----
        #pragma unroll
        for (int it = 0; it < 7; it++) {
            if (it == 6 && !tail_ok) break;
            float4 v = (it == 0 && dlane) ? dptr[kc * 8] : sp[it * 128];
            uint32_t h01 = pack_bf16x2(v.x, v.y);
            uint32_t h23 = pack_bf16x2(v.z, v.w);
            uint32_t l01 = pack_bf16x2(v.x - bf_lo(h01), v.y - bf_hi(h01));
            uint32_t l23 = pack_bf16x2(v.z - bf_lo(h23), v.w - bf_hi(h23));
            uint32_t so = sOff0 + it * (4 * TSTRIDE);
            asm volatile("st.shared.v2.b32 [%0], {%1, %2};"
                         :: "r"(hiBase + so), "r"(h01), "r"(h23));
            asm volatile("st.shared.v2.b32 [%0], {%1, %2};"
                         :: "r"(loBase + so), "r"(l01), "r"(l23));
            if (it == 0 && dlane && r0 == 0) {    // lanes 0..7: dense passthrough
                out2[kc * 16 + lane * 2]     = make_float2(v.x, v.y);
                out2[kc * 16 + lane * 2 + 1] = make_float2(v.z, v.w);
            }
        }
        __syncwarp();

        // ---- compute: 2 k-steps x (4 LDSM.x4 + 18 HMMA) ----
        #pragma unroll
        for (int ks = 0; ks < 2; ks++) {
            uint32_t off0 = (uint32_t)(lrow * TSTRIDE + (2 * ks + lu) * 16);
            uint32_t H0[4], H1[4], L0[4], L1[4];
            ldsm4(H0, hiBase + off0);
            ldsm4(H1, hiBase + off0 + 16 * TSTRIDE);
            ldsm4(L0, loBase + off0);
            ldsm4(L1, loBase + off0 + 16 * TSTRIDE);
            do_pair(c00, c01, c02, c03, c12, c13, H0, H1, H0, H1);  // hi.hi
            do_pair(c00, c01, c02, c03, c12, c13, H0, H1, L0, L1);  // hi.lo
            do_pair(c00, c01, c02, c03, c12, c13, L0, L1, H0, H1);  // lo.hi
        }
        __syncwarp();    // WAR before restaging
    }

    // ---- epilogue: frags -> smem gram[32][33], then triu scatter ----
    float* gstage = reinterpret_cast<float*>(smem + warp * WBYTES);
    {
        const int fr = lane >> 2;                 // 0..7
        const int fc = 2 * (lane & 3);            // 0,2,4,6
        float* t[6] = {c00, c01, c02, c03, c12, c13};
        const int mi[6] = {0, 0, 0, 0, 16, 16};
        const int nj[6] = {0, 8, 16, 24, 16, 24};
        #pragma unroll
        for (int q = 0; q < 6; q++) {
            int r = mi[q] + fr, c = nj[q] + fc;
            gstage[r * 33 + c]           = t[q][0];
            gstage[r * 33 + c + 1]       = t[q][1];
            gstage[(r + 8) * 33 + c]     = t[q][2];
            gstage[(r + 8) * 33 + c + 1] = t[q][3];
        }
    }
    __syncwarp();

    {   // lane j writes gram[i][j] for i <= j; per-i stores are coalesced
        float* orow = out + (long long)b * OUTW + 128;
        #pragma unroll 1
        for (int i = 0; i < 27; i++) {
            if (lane < 27 && i <= lane) {
                orow[26 * i - (i * (i - 1)) / 2 + lane] = gstage[i * 33 + lane];
            }
        }
    }
}

extern "C" void kernel_launch(void* const* d_in, const int* in_sizes, int n_in,
                              void* d_out, int out_size)
{
    const float4* dense4  = (const float4*)d_in[0];
    const float4* sparse4 = (const float4*)d_in[1];
    float*        out     = (float*)d_out;

    int B = in_sizes[0] / 128;
    int grid = (B + WPC - 1) / WPC;
    size_t smem_sz = (size_t)WPC * WBYTES;        // 20,480 B

    dot_interact_mma<<<grid, THREADS, smem_sz>>>(dense4, sparse4, out, B);
    (void)n_in; (void)out_size;
}